// round 12
// baseline (speedup 1.0000x reference)
#include <cuda_runtime.h>
#include <cuda_fp16.h>
#include <cstdint>

#define V      32000
#define CHI    64
#define TT     512
#define BB     8
#define KTOT   4096
#define MROWS  4096
#define NBLK   125          // V / 256
#define LN_EPS 1e-5f

// ---- scratch (device globals; no allocs allowed) ----
__device__ float  d_ml[TT * CHI];
__device__ float  d_mr[TT * CHI];
__device__ float  d_Hmod[MROWS * CHI];
__device__ __half d_G[(size_t)MROWS * KTOT];
__device__ __half d_coreh[(size_t)V * KTOT];
__device__ float  d_pm[(size_t)NBLK * MROWS];
__device__ float  d_ps[(size_t)NBLK * MROWS];
__device__ float  d_tgl[MROWS];
__device__ float  d_rowloss[MROWS];

// ---- helpers ----
__device__ __forceinline__ uint32_t smem_u32(const void* p) {
    uint32_t a;
    asm("{ .reg .u64 t; cvta.to.shared.u64 t, %1; cvt.u32.u64 %0, t; }" : "=r"(a) : "l"(p));
    return a;
}
__device__ __forceinline__ void cp_async16(uint32_t s, const void* g) {
    asm volatile("cp.async.cg.shared.global [%0], [%1], 16;\n" :: "r"(s), "l"(g) : "memory");
}
#define CP_COMMIT() asm volatile("cp.async.commit_group;\n" ::: "memory")
#define CP_WAIT1()  asm volatile("cp.async.wait_group 1;\n" ::: "memory")

#define LDSM4(r, addr) \
    asm volatile("ldmatrix.sync.aligned.m8n8.x4.shared.b16 {%0,%1,%2,%3}, [%4];" \
        : "=r"((r)[0]), "=r"((r)[1]), "=r"((r)[2]), "=r"((r)[3]) : "r"(addr))

// fp16-accumulator HMMA: 2x rate of the f32-accum form on the legacy pipe
#define MMA16816H(d, a, b0, b1) \
    asm volatile("mma.sync.aligned.m16n8k16.row.col.f16.f16.f16.f16 " \
        "{%0,%1}, {%2,%3,%4,%5}, {%6,%7}, {%0,%1};" \
        : "+r"((d)[0]), "+r"((d)[1]) \
        : "r"((a)[0]), "r"((a)[1]), "r"((a)[2]), "r"((a)[3]), "r"(b0), "r"(b1))

__device__ __forceinline__ float fast_exp(float x) {   // exp(x), x <= 0
    if (x < -87.0f) return 0.f;
    float y = x * 1.44269504f;
    float n = rintf(y);
    float f = y - n;
    float p = 1.53938e-4f;
    p = fmaf(p, f, 1.33336e-3f);
    p = fmaf(p, f, 9.61813e-3f);
    p = fmaf(p, f, 5.55041e-2f);
    p = fmaf(p, f, 2.402265e-1f);
    p = fmaf(p, f, 6.931472e-1f);
    p = fmaf(p, f, 1.0f);
    return p * __int_as_float(((int)n + 127) << 23);
}

// ---- kernel 1: position MLP -> ml, mr ----
__global__ void mod_kernel(const float* __restrict__ pos,
                           const float* __restrict__ W1, const float* __restrict__ b1,
                           const float* __restrict__ W2, const float* __restrict__ b2) {
    int t = blockIdx.x, tid = threadIdx.x;   // 512 x 128
    __shared__ float pe[64];
    __shared__ float hm[128];
    if (tid < 64) pe[tid] = pos[t * 64 + tid];
    __syncthreads();
    float s = b1[tid];
#pragma unroll
    for (int p = 0; p < 64; p++) s += pe[p] * W1[p * 128 + tid];
    hm[tid] = s * 0.5f * (1.0f + erff(s * 0.7071067811865475f));
    __syncthreads();
    float s2 = b2[tid];
#pragma unroll
    for (int h = 0; h < 128; h++) s2 += hm[h] * W2[h * 128 + tid];
    float vm = 1.0f + 0.5f * tanhf(s2);
    if (tid < 64) d_ml[t * 64 + tid] = vm;
    else          d_mr[t * 64 + (tid - 64)] = vm;
}

// ---- kernel 2: core fp32 [i][v][j] -> fp16 coreW [v][i*64+j] ----
__global__ void convert_core_kernel(const float* __restrict__ core) {
    long long n2 = (long long)blockIdx.x * blockDim.x + threadIdx.x;  // V*KTOT/2
    int v = (int)(n2 >> 11);
    int k = ((int)n2 & 2047) * 2;
    int i = k >> 6, j = k & 63;
    const float2 f = *reinterpret_cast<const float2*>(
        core + (size_t)i * ((size_t)V * 64) + (size_t)v * 64 + j);
    reinterpret_cast<__half2*>(d_coreh)[n2] = __floats2half2_rn(f.x, f.y);
}

// ---- kernel 3: sequential scan ----
__global__ void scan_kernel(const int* __restrict__ ids, const float* __restrict__ core,
                            const float* __restrict__ h0,
                            const float* __restrict__ gam, const float* __restrict__ bet) {
    __shared__ float sl[2][64 * 64];
    __shared__ float hm[64];
    __shared__ float red[4];
    int b = blockIdx.x, tid = threadIdx.x, lane = tid & 31, wid = tid >> 5;
    float h = h0[tid], g = gam[tid], be = bet[tid];
    uint32_t sb[2] = { smem_u32(&sl[0][0]), smem_u32(&sl[1][0]) };
    {
        int x = ids[b * TT];
        for (int gq = tid; gq < 1024; gq += 64) {
            int i = gq >> 4, c = gq & 15;
            cp_async16(sb[0] + i * 256 + c * 16,
                       core + (size_t)i * ((size_t)V * 64) + (size_t)x * 64 + c * 4);
        }
        CP_COMMIT();
    }
    for (int t = 0; t < TT; t++) {
        if (t + 1 < TT) {
            int x = ids[b * TT + t + 1];
            uint32_t base = sb[(t + 1) & 1];
            for (int gq = tid; gq < 1024; gq += 64) {
                int i = gq >> 4, c = gq & 15;
                cp_async16(base + i * 256 + c * 16,
                           core + (size_t)i * ((size_t)V * 64) + (size_t)x * 64 + c * 4);
            }
        }
        CP_COMMIT();
        CP_WAIT1();
        float hv = h * d_ml[t * 64 + tid];
        hm[tid] = hv;
        d_Hmod[(t * 8 + b) * 64 + tid] = hv;
        __syncthreads();
        const float* s = &sl[t & 1][0];
        float y = 0.f;
#pragma unroll
        for (int i = 0; i < 64; i++) y += hm[i] * s[i * 64 + tid];
        y *= d_mr[t * 64 + tid];
        float su = y, q = y * y;
#pragma unroll
        for (int off = 16; off; off >>= 1) {
            su += __shfl_xor_sync(0xffffffffu, su, off);
            q  += __shfl_xor_sync(0xffffffffu, q,  off);
        }
        if (lane == 0) { red[wid * 2] = su; red[wid * 2 + 1] = q; }
        __syncthreads();
        float S = red[0] + red[2], Q = red[1] + red[3];
        float mu = S * (1.f / 64.f);
        float var = Q * (1.f / 64.f) - mu * mu;
        h = (y - mu) * rsqrtf(var + LN_EPS) * g + be;
        __syncthreads();
    }
}

// ---- kernel 4: G[r][i*64+j] = fp16(Hmod[r][i] * mr[t][j]), r=t*8+b ----
__global__ void buildG_kernel() {
    int n2 = blockIdx.x * blockDim.x + threadIdx.x;   // MROWS*KTOT/2
    int r = n2 >> 11;
    int k = (n2 & 2047) * 2;
    int i = k >> 6, j = k & 63;
    int t = r >> 3;
    float hv = d_Hmod[r * 64 + i];
    reinterpret_cast<__half2*>(d_G)[n2] =
        __floats2half2_rn(hv * d_mr[t * 64 + j], hv * d_mr[t * 64 + j + 1]);
}

// ---- kernel 5: mma.sync GEMM 128x256, BK=64, 3-stage, fp16 split accumulation ----
// stage s: A (128x64 half, 16KB) @ s*49152, B (256x64 half, 32KB) @ s*49152+16384
// epilogue reuses bytes [0,131072) for the fp32 accum tile, bias at 131072.
#define ST_A(s)  ((uint32_t)(s) * 49152u)
#define ST_B(s)  ((uint32_t)(s) * 49152u + 16384u)
#define SM_TOTAL 147456

__global__ void __launch_bounds__(512, 1)
gemm_kernel(const int* __restrict__ tgt, const float* __restrict__ bias) {
    extern __shared__ __align__(16) char dsm[];
    const int tid  = threadIdx.x;
    const int w    = tid >> 5;
    const int lane = tid & 31;
    const int wm   = w & 1;          // 2 x 64 rows
    const int wn   = w >> 1;         // 8 x 32 cols
    const int M0   = blockIdx.x * 128;   // M fastest -> B tile L2 reuse
    const int N0   = blockIdx.y * 256;

    const uint32_t sbase = smem_u32(dsm);

    float acc[4][4][4];              // fp32 master accumulators
#pragma unroll
    for (int i = 0; i < 4; i++)
#pragma unroll
        for (int j = 0; j < 4; j++)
#pragma unroll
            for (int c = 0; c < 4; c++) acc[i][j][c] = 0.f;

    uint32_t hacc[4][4][2];          // fp16 accumulators (flushed every 2 tiles = K=128)
#pragma unroll
    for (int i = 0; i < 4; i++)
#pragma unroll
        for (int j = 0; j < 4; j++) { hacc[i][j][0] = 0u; hacc[i][j][1] = 0u; }

#define LOAD_STAGE(slot, kt) do {                                                  \
        _Pragma("unroll")                                                          \
        for (int it = 0; it < 2; it++) {  /* A: 1024 x 16B */                      \
            int idx = tid + it * 512;                                              \
            int row = idx >> 3, c = idx & 7;                                       \
            uint32_t o = (uint32_t)(row * 128 + c * 16);                           \
            o ^= (uint32_t)((row & 7) << 4);                                       \
            cp_async16(sbase + ST_A(slot) + o,                                     \
                       d_G + (size_t)(M0 + row) * KTOT + (kt) * 64 + c * 8);       \
        }                                                                          \
        _Pragma("unroll")                                                          \
        for (int it = 0; it < 4; it++) {  /* B: 2048 x 16B */                      \
            int idx = tid + it * 512;                                              \
            int row = idx >> 3, c = idx & 7;                                       \
            uint32_t o = (uint32_t)(row * 128 + c * 16);                           \
            o ^= (uint32_t)((row & 7) << 4);                                       \
            cp_async16(sbase + ST_B(slot) + o,                                     \
                       d_coreh + (size_t)(N0 + row) * KTOT + (kt) * 64 + c * 8);   \
        }                                                                          \
    } while (0)

    LOAD_STAGE(0, 0);
    CP_COMMIT();
    LOAD_STAGE(1, 1);
    CP_COMMIT();

    const int lr = lane & 15, lc = lane >> 4;
    const int kTiles = KTOT / 64;    // 64
    for (int kt = 0; kt < kTiles; kt++) {
        CP_WAIT1();                  // stage kt resident
        __syncthreads();
        if (kt + 2 < kTiles) LOAD_STAGE((kt + 2) % 3, kt + 2);
        CP_COMMIT();

        const uint32_t ab = sbase + ST_A(kt % 3);
        const uint32_t bb = sbase + ST_B(kt % 3);
#pragma unroll
        for (int ks = 0; ks < 4; ks++) {
            const int koff = ks * 32 + lc * 16;   // byte offset in 128B row
            uint32_t Af[4][4];
#pragma unroll
            for (int i = 0; i < 4; i++) {
                int row = wm * 64 + i * 16 + lr;
                uint32_t o = (uint32_t)(row * 128 + koff);
                o ^= (uint32_t)((row & 7) << 4);
                LDSM4(Af[i], ab + o);
            }
            uint32_t Bf[2][4];
#pragma unroll
            for (int j2 = 0; j2 < 2; j2++) {
                int row = wn * 32 + j2 * 16 + lr;
                uint32_t o = (uint32_t)(row * 128 + koff);
                o ^= (uint32_t)((row & 7) << 4);
                LDSM4(Bf[j2], bb + o);
            }
#pragma unroll
            for (int i = 0; i < 4; i++)
#pragma unroll
                for (int j8 = 0; j8 < 4; j8++)
                    MMA16816H(hacc[i][j8], Af[i],
                              Bf[j8 >> 1][j8 & 1], Bf[j8 >> 1][(j8 & 1) + 2]);
        }
        if (kt & 1) {                // flush fp16 partials into fp32 every K=128
#pragma unroll
            for (int i = 0; i < 4; i++)
#pragma unroll
                for (int j8 = 0; j8 < 4; j8++) {
                    float2 f0 = __half22float2(*(__half2*)&hacc[i][j8][0]);
                    float2 f1 = __half22float2(*(__half2*)&hacc[i][j8][1]);
                    acc[i][j8][0] += f0.x;
                    acc[i][j8][1] += f0.y;
                    acc[i][j8][2] += f1.x;
                    acc[i][j8][3] += f1.y;
                    hacc[i][j8][0] = 0u;
                    hacc[i][j8][1] = 0u;
                }
        }
        __syncthreads();
    }

    // ---- epilogue: accums -> smem, fused partial softmax ----
    float* accs = (float*)dsm;
    float* bs   = (float*)(dsm + 131072);
    if (tid < 256) bs[tid] = bias[N0 + tid];
    {
        int t4 = lane >> 2, t2 = (lane & 3) * 2;
#pragma unroll
        for (int i = 0; i < 4; i++) {
            int r0 = wm * 64 + i * 16 + t4;
#pragma unroll
            for (int j8 = 0; j8 < 4; j8++) {
                int gc = wn * 32 + j8 * 8 + t2;
                *(float2*)(accs + r0 * 256 + gc)       = make_float2(acc[i][j8][0], acc[i][j8][1]);
                *(float2*)(accs + (r0 + 8) * 256 + gc) = make_float2(acc[i][j8][2], acc[i][j8][3]);
            }
        }
    }
    __syncthreads();

    {
        int rl = tid >> 2, q = tid & 3;            // row-local, quarter (64 cols)
        int r = M0 + rl;
        const float* rowp = accs + rl * 256 + q * 64;
        const float* bq = bs + q * 64;
        float m = -1e30f;
#pragma unroll
        for (int c = 0; c < 64; c++) m = fmaxf(m, rowp[c] + bq[c]);
        float s = 0.f;
#pragma unroll
        for (int c = 0; c < 64; c++) s += fast_exp(rowp[c] + bq[c] - m);
#pragma unroll
        for (int off = 1; off < 4; off <<= 1) {
            float m2 = __shfl_xor_sync(0xffffffffu, m, off);
            float s2 = __shfl_xor_sync(0xffffffffu, s, off);
            float M = fmaxf(m, m2);
            s = s * fast_exp(m - M) + s2 * fast_exp(m2 - M);
            m = M;
        }
        int tg = tgt[(r & 7) * TT + (r >> 3)];
        int jj = tg - N0 - q * 64;
        if (jj >= 0 && jj < 64) d_tgl[r] = rowp[jj] + bq[jj];
        if (q == 0) {
            d_pm[(size_t)blockIdx.y * MROWS + r] = m;
            d_ps[(size_t)blockIdx.y * MROWS + r] = s;
        }
    }
}

// ---- kernel 6: combine partials -> per-row loss ----
__global__ void combine_kernel() {
    int r = blockIdx.x, tid = threadIdx.x;   // 4096 x 128
    __shared__ float sm[128], ss[128];
    float m = (tid < NBLK) ? d_pm[(size_t)tid * MROWS + r] : -3e38f;
    float s = (tid < NBLK) ? d_ps[(size_t)tid * MROWS + r] : 0.f;
    sm[tid] = m;
    __syncthreads();
    for (int off = 64; off; off >>= 1) {
        if (tid < off) sm[tid] = fmaxf(sm[tid], sm[tid + off]);
        __syncthreads();
    }
    float M = sm[0];
    ss[tid] = s * fast_exp(m - M);
    __syncthreads();
    for (int off = 64; off; off >>= 1) {
        if (tid < off) ss[tid] += ss[tid + off];
        __syncthreads();
    }
    if (tid == 0) d_rowloss[r] = (M + logf(ss[0])) - d_tgl[r];
}

// ---- kernel 7: mean ----
__global__ void reduce_kernel(float* __restrict__ out) {
    int tid = threadIdx.x;
    float s = 0.f;
    for (int i = tid; i < MROWS; i += 1024) s += d_rowloss[i];
#pragma unroll
    for (int off = 16; off; off >>= 1) s += __shfl_xor_sync(0xffffffffu, s, off);
    __shared__ float sh[32];
    if ((tid & 31) == 0) sh[tid >> 5] = s;
    __syncthreads();
    if (tid < 32) {
        float v = sh[tid];
#pragma unroll
        for (int off = 16; off; off >>= 1) v += __shfl_xor_sync(0xffffffffu, v, off);
        if (tid == 0) out[0] = v * (1.f / MROWS);
    }
}

extern "C" void kernel_launch(void* const* d_in, const int* in_sizes, int n_in,
                              void* d_out, int out_size) {
    const int*   input_ids  = (const int*)  d_in[0];
    const int*   target_ids = (const int*)  d_in[1];
    const float* core       = (const float*)d_in[2];
    const float* h0         = (const float*)d_in[3];
    const float* pos_embed  = (const float*)d_in[4];
    const float* W1         = (const float*)d_in[5];
    const float* b1         = (const float*)d_in[6];
    const float* W2         = (const float*)d_in[7];
    const float* b2         = (const float*)d_in[8];
    const float* obias      = (const float*)d_in[9];
    const float* ln_gamma   = (const float*)d_in[10];
    const float* ln_beta    = (const float*)d_in[11];
    float* out = (float*)d_out;

    cudaFuncSetAttribute(gemm_kernel, cudaFuncAttributeMaxDynamicSharedMemorySize, SM_TOTAL);

    mod_kernel<<<TT, 128>>>(pos_embed, W1, b1, W2, b2);
    convert_core_kernel<<<(int)(((size_t)V * KTOT / 2) / 256), 256>>>(core);
    scan_kernel<<<BB, 64>>>(input_ids, core, h0, ln_gamma, ln_beta);
    buildG_kernel<<<(MROWS * KTOT / 2) / 256, 256>>>();
    gemm_kernel<<<dim3(MROWS / 128, NBLK), 512, SM_TOTAL>>>(target_ids, obias);
    combine_kernel<<<MROWS, 128>>>();
    reduce_kernel<<<1, 1024>>>(out);
}

// round 14
// speedup vs baseline: 1.5406x; 1.5406x over previous
#include <cuda_runtime.h>
#include <cuda_fp16.h>
#include <cstdint>

#define V      32000
#define CHI    64
#define TT     512
#define BB     8
#define KTOT   4096
#define MROWS  4096
#define NBLK   125          // V / 256
#define THALF  256          // t values per half-pass
#define LN_EPS 1e-5f

// ---- scratch (device globals; no allocs allowed) ----
__device__ float  d_ml[TT * CHI];
__device__ float  d_mr[TT * CHI];
__device__ __half d_mrh[TT * CHI];
__device__ float  d_Hmod[MROWS * CHI];
__device__ __half d_coreh2[(size_t)CHI * V * CHI];       // fp16 core, layout [i][v][j]
__device__ __half d_D[(size_t)THALF * V * CHI];          // D[tloc][v][i], 1.05 GB
__device__ float  d_pm[(size_t)NBLK * MROWS];
__device__ float  d_ps[(size_t)NBLK * MROWS];
__device__ float  d_tgl[MROWS];
__device__ float  d_rowloss[MROWS];

// ---- helpers ----
__device__ __forceinline__ uint32_t smem_u32(const void* p) {
    uint32_t a;
    asm("{ .reg .u64 t; cvta.to.shared.u64 t, %1; cvt.u32.u64 %0, t; }" : "=r"(a) : "l"(p));
    return a;
}
__device__ __forceinline__ void cp_async16(uint32_t s, const void* g) {
    asm volatile("cp.async.cg.shared.global [%0], [%1], 16;\n" :: "r"(s), "l"(g) : "memory");
}
#define CP_COMMIT() asm volatile("cp.async.commit_group;\n" ::: "memory")
#define CP_WAIT1()  asm volatile("cp.async.wait_group 1;\n" ::: "memory")
#define CP_WAIT0()  asm volatile("cp.async.wait_group 0;\n" ::: "memory")

#define LDSM4(r, addr) \
    asm volatile("ldmatrix.sync.aligned.m8n8.x4.shared.b16 {%0,%1,%2,%3}, [%4];" \
        : "=r"((r)[0]), "=r"((r)[1]), "=r"((r)[2]), "=r"((r)[3]) : "r"(addr))

#define MMA16816(d, a, b0, b1) \
    asm volatile("mma.sync.aligned.m16n8k16.row.col.f32.f16.f16.f32 " \
        "{%0,%1,%2,%3}, {%4,%5,%6,%7}, {%8,%9}, {%0,%1,%2,%3};" \
        : "+f"((d)[0]), "+f"((d)[1]), "+f"((d)[2]), "+f"((d)[3]) \
        : "r"((a)[0]), "r"((a)[1]), "r"((a)[2]), "r"((a)[3]), "r"(b0), "r"(b1))

__device__ __forceinline__ float fast_exp(float x) {   // exp(x), x <= 0
    if (x < -87.0f) return 0.f;
    float y = x * 1.44269504f;
    float n = rintf(y);
    float f = y - n;
    float p = 1.53938e-4f;
    p = fmaf(p, f, 1.33336e-3f);
    p = fmaf(p, f, 9.61813e-3f);
    p = fmaf(p, f, 5.55041e-2f);
    p = fmaf(p, f, 2.402265e-1f);
    p = fmaf(p, f, 6.931472e-1f);
    p = fmaf(p, f, 1.0f);
    return p * __int_as_float(((int)n + 127) << 23);
}

// ---- kernel 1: position MLP -> ml, mr (+ fp16 mr) ----
__global__ void mod_kernel(const float* __restrict__ pos,
                           const float* __restrict__ W1, const float* __restrict__ b1,
                           const float* __restrict__ W2, const float* __restrict__ b2) {
    int t = blockIdx.x, tid = threadIdx.x;   // 512 x 128
    __shared__ float pe[64];
    __shared__ float hm[128];
    if (tid < 64) pe[tid] = pos[t * 64 + tid];
    __syncthreads();
    float s = b1[tid];
#pragma unroll
    for (int p = 0; p < 64; p++) s += pe[p] * W1[p * 128 + tid];
    hm[tid] = s * 0.5f * (1.0f + erff(s * 0.7071067811865475f));
    __syncthreads();
    float s2 = b2[tid];
#pragma unroll
    for (int h = 0; h < 128; h++) s2 += hm[h] * W2[h * 128 + tid];
    float vm = 1.0f + 0.5f * tanhf(s2);
    if (tid < 64) d_ml[t * 64 + tid] = vm;
    else {
        d_mr[t * 64 + (tid - 64)]  = vm;
        d_mrh[t * 64 + (tid - 64)] = __float2half(vm);
    }
}

// ---- kernel 2: core fp32 -> fp16, identity layout [i][v][j] ----
__global__ void convert_core_kernel(const float* __restrict__ core) {
    long long n2 = (long long)blockIdx.x * blockDim.x + threadIdx.x;  // CHI*V*CHI/2
    const float2 f = reinterpret_cast<const float2*>(core)[n2];
    reinterpret_cast<__half2*>(d_coreh2)[n2] = __floats2half2_rn(f.x, f.y);
}

// ---- kernel 3: sequential scan (unchanged, verified) ----
__global__ void scan_kernel(const int* __restrict__ ids, const float* __restrict__ core,
                            const float* __restrict__ h0,
                            const float* __restrict__ gam, const float* __restrict__ bet) {
    __shared__ float sl[2][64 * 64];
    __shared__ float hm[64];
    __shared__ float red[4];
    int b = blockIdx.x, tid = threadIdx.x, lane = tid & 31, wid = tid >> 5;
    float h = h0[tid], g = gam[tid], be = bet[tid];
    uint32_t sb[2] = { smem_u32(&sl[0][0]), smem_u32(&sl[1][0]) };
    {
        int x = ids[b * TT];
        for (int gq = tid; gq < 1024; gq += 64) {
            int i = gq >> 4, c = gq & 15;
            cp_async16(sb[0] + i * 256 + c * 16,
                       core + (size_t)i * ((size_t)V * 64) + (size_t)x * 64 + c * 4);
        }
        CP_COMMIT();
    }
    for (int t = 0; t < TT; t++) {
        if (t + 1 < TT) {
            int x = ids[b * TT + t + 1];
            uint32_t base = sb[(t + 1) & 1];
            for (int gq = tid; gq < 1024; gq += 64) {
                int i = gq >> 4, c = gq & 15;
                cp_async16(base + i * 256 + c * 16,
                           core + (size_t)i * ((size_t)V * 64) + (size_t)x * 64 + c * 4);
            }
        }
        CP_COMMIT();
        CP_WAIT1();
        float hv = h * d_ml[t * 64 + tid];
        hm[tid] = hv;
        d_Hmod[(t * 8 + b) * 64 + tid] = hv;
        __syncthreads();
        const float* s = &sl[t & 1][0];
        float y = 0.f;
#pragma unroll
        for (int i = 0; i < 64; i++) y += hm[i] * s[i * 64 + tid];
        y *= d_mr[t * 64 + tid];
        float su = y, q = y * y;
#pragma unroll
        for (int off = 16; off; off >>= 1) {
            su += __shfl_xor_sync(0xffffffffu, su, off);
            q  += __shfl_xor_sync(0xffffffffu, q,  off);
        }
        if (lane == 0) { red[wid * 2] = su; red[wid * 2 + 1] = q; }
        __syncthreads();
        float S = red[0] + red[2], Q = red[1] + red[3];
        float mu = S * (1.f / 64.f);
        float var = Q * (1.f / 64.f) - mu * mu;
        h = (y - mu) * rsqrtf(var + LN_EPS) * g + be;
        __syncthreads();
    }
}

// ---- kernel 4 (pass 1): D[tloc][v][i] = sum_j mr[t][j] * core[i][v][j] ----
// per-v GEMM: M=t (tile 128), N=i (64), K=j (64). Block: 8 v's, 128 threads.
// smem: A (mr tile, 128x64 half, 16KB) @0 ; B[vv] (64x64 half, 8KB) @16384+vv*8192
#define P1_SMEM (16384 + 8 * 8192)
__global__ void __launch_bounds__(128)
pass1_kernel(int t_base) {
    extern __shared__ __align__(16) char p1sm[];
    const int tid = threadIdx.x, w = tid >> 5, lane = tid & 31;
    const int lr = lane & 15, lc = lane >> 4;
    const int t0 = blockIdx.x * 128;        // local t within half [0,256)
    const int vg = blockIdx.y * 8;
    const uint32_t sb = smem_u32(p1sm);

    // load A: 128 rows x 128B (swizzled)
#pragma unroll
    for (int it = 0; it < 8; it++) {
        int idx = tid + it * 128;
        int row = idx >> 3, c = idx & 7;
        uint32_t o = (uint32_t)(row * 128 + c * 16);
        o ^= (uint32_t)((row & 7) << 4);
        cp_async16(sb + o, d_mrh + (size_t)(t_base + t0 + row) * 64 + c * 8);
    }
    // load B: 8 v x 64 rows x 128B
#pragma unroll
    for (int it = 0; it < 32; it++) {
        int idx = tid + it * 128;
        int vv = idx >> 9, rem = idx & 511;
        int row = rem >> 3, c = rem & 7;
        uint32_t o = (uint32_t)(row * 128 + c * 16);
        o ^= (uint32_t)((row & 7) << 4);
        cp_async16(sb + 16384u + (uint32_t)vv * 8192u + o,
                   d_coreh2 + ((size_t)row * V + (vg + vv)) * 64 + c * 8);
    }
    CP_COMMIT();
    CP_WAIT0();
    __syncthreads();

    const int t4 = lane >> 2, t2 = (lane & 3) * 2;
    for (int vv = 0; vv < 8; vv++) {
        float acc[2][8][4];
#pragma unroll
        for (int im = 0; im < 2; im++)
#pragma unroll
            for (int j8 = 0; j8 < 8; j8++)
#pragma unroll
                for (int c = 0; c < 4; c++) acc[im][j8][c] = 0.f;

        const uint32_t bb = sb + 16384u + (uint32_t)vv * 8192u;
#pragma unroll
        for (int ks = 0; ks < 4; ks++) {
            const int koff = ks * 32 + lc * 16;
            uint32_t Af[2][4];
#pragma unroll
            for (int im = 0; im < 2; im++) {
                int row = w * 32 + im * 16 + lr;
                uint32_t o = (uint32_t)(row * 128 + koff);
                o ^= (uint32_t)((row & 7) << 4);
                LDSM4(Af[im], sb + o);
            }
            uint32_t Bf[4][4];
#pragma unroll
            for (int jn = 0; jn < 4; jn++) {
                int row = jn * 16 + lr;
                uint32_t o = (uint32_t)(row * 128 + koff);
                o ^= (uint32_t)((row & 7) << 4);
                LDSM4(Bf[jn], bb + o);
            }
#pragma unroll
            for (int im = 0; im < 2; im++)
#pragma unroll
                for (int j8 = 0; j8 < 8; j8++)
                    MMA16816(acc[im][j8], Af[im],
                             Bf[j8 >> 1][j8 & 1], Bf[j8 >> 1][(j8 & 1) + 2]);
        }
        // store fragments to D[tloc][v][i] (i contiguous, half2)
        const size_t vbase = (size_t)(vg + vv) * 64;
#pragma unroll
        for (int im = 0; im < 2; im++) {
            int r0 = t0 + w * 32 + im * 16 + t4;
#pragma unroll
            for (int j8 = 0; j8 < 8; j8++) {
                int gc = j8 * 8 + t2;
                *reinterpret_cast<__half2*>(d_D + (size_t)r0 * (V * 64) + vbase + gc) =
                    __floats2half2_rn(acc[im][j8][0], acc[im][j8][1]);
                *reinterpret_cast<__half2*>(d_D + (size_t)(r0 + 8) * (V * 64) + vbase + gc) =
                    __floats2half2_rn(acc[im][j8][2], acc[im][j8][3]);
            }
        }
    }
}

// ---- kernel 5 (pass 2): logits[(t,b),v] = sum_i hmod[(t,b),i] * D[t][v][i], fused softmax
// block = (vblk 256 v's, one t). M=16 (8 valid b rows), N=256, K=64.
__global__ void __launch_bounds__(128)
pass2_kernel(int t_base, const int* __restrict__ tgt, const float* __restrict__ bias) {
    __shared__ __align__(16) __half Dt[256 * 64];   // rows v (128B, swizzled)
    __shared__ __align__(16) __half Ah[16 * 64];    // rows b (128B, swizzled)
    __shared__ float accs[8 * 256];
    __shared__ float bs[256];
    const int tid = threadIdx.x, w = tid >> 5, lane = tid & 31;
    const int lr = lane & 15, lc = lane >> 4;
    const int vblk = blockIdx.x, v0 = vblk * 256;
    const int tloc = blockIdx.y, tg_t = t_base + tloc;
    const uint32_t db = smem_u32(Dt), abh = smem_u32(Ah);

    // load D tile: 256 rows x 128B
#pragma unroll
    for (int it = 0; it < 16; it++) {
        int idx = tid + it * 128;
        int row = idx >> 3, c = idx & 7;
        uint32_t o = (uint32_t)(row * 128 + c * 16);
        o ^= (uint32_t)((row & 7) << 4);
        cp_async16(db + o, d_D + ((size_t)tloc * V + (v0 + row)) * 64 + c * 8);
    }
    CP_COMMIT();
    // build A: rows 0-7 = fp16(hmod[tg_t*8+b]), rows 8-15 = 0 (swizzled stores)
    for (int idx = tid; idx < 1024; idx += 128) {
        int b = idx >> 6, i = idx & 63;
        __half hv = (b < 8) ? __float2half(d_Hmod[(size_t)(tg_t * 8 + b) * 64 + i])
                            : __half(0.f);
        uint32_t o = (uint32_t)(b * 128 + i * 2);
        o ^= (uint32_t)((b & 7) << 4);
        *reinterpret_cast<__half*>(reinterpret_cast<char*>(Ah) + o) = hv;
    }
    bs[tid]       = bias[v0 + tid];
    bs[tid + 128] = bias[v0 + tid + 128];
    CP_WAIT0();
    __syncthreads();

    float acc[8][4];
#pragma unroll
    for (int j8 = 0; j8 < 8; j8++)
#pragma unroll
        for (int c = 0; c < 4; c++) acc[j8][c] = 0.f;

#pragma unroll
    for (int ks = 0; ks < 4; ks++) {
        const int koff = ks * 32 + lc * 16;
        uint32_t Af[4];
        {
            int row = lr;
            uint32_t o = (uint32_t)(row * 128 + koff);
            o ^= (uint32_t)((row & 7) << 4);
            LDSM4(Af, abh + o);
        }
        uint32_t Bf[4][4];
#pragma unroll
        for (int jn = 0; jn < 4; jn++) {
            int row = w * 64 + jn * 16 + lr;
            uint32_t o = (uint32_t)(row * 128 + koff);
            o ^= (uint32_t)((row & 7) << 4);
            LDSM4(Bf[jn], db + o);
        }
#pragma unroll
        for (int j8 = 0; j8 < 8; j8++)
            MMA16816(acc[j8], Af, Bf[j8 >> 1][j8 & 1], Bf[j8 >> 1][(j8 & 1) + 2]);
    }
    // store valid rows (c0,c1: row t4 in 0..7) to accs
    {
        int t4 = lane >> 2, t2 = (lane & 3) * 2;
#pragma unroll
        for (int j8 = 0; j8 < 8; j8++) {
            int gc = w * 64 + j8 * 8 + t2;
            accs[t4 * 256 + gc]     = acc[j8][0];
            accs[t4 * 256 + gc + 1] = acc[j8][1];
        }
    }
    __syncthreads();

    // fused partial softmax: 8 rows x 256 cols; 16 threads per row
    {
        int row = tid >> 4, seg = tid & 15;
        int r = tg_t * 8 + row;                      // global row (t*8+b)
        int tg = tgt[row * TT + tg_t];
        float m = -1e30f, s = 0.f, tval = 0.f;
        bool hit = false;
#pragma unroll
        for (int c0 = 0; c0 < 16; c0++) {
            int col = seg * 16 + c0;
            float x = accs[row * 256 + col] + bs[col];
            if (v0 + col == tg) { tval = x; hit = true; }
            m = fmaxf(m, x);
        }
        float s0 = 0.f;
#pragma unroll
        for (int c0 = 0; c0 < 16; c0++) {
            int col = seg * 16 + c0;
            s0 += fast_exp(accs[row * 256 + col] + bs[col] - m);
        }
        s = s0;
#pragma unroll
        for (int off = 1; off < 16; off <<= 1) {
            float m2 = __shfl_xor_sync(0xffffffffu, m, off);
            float s2 = __shfl_xor_sync(0xffffffffu, s, off);
            float M = fmaxf(m, m2);
            s = s * fast_exp(m - M) + s2 * fast_exp(m2 - M);
            m = M;
        }
        if (seg == 0) {
            d_pm[(size_t)vblk * MROWS + r] = m;
            d_ps[(size_t)vblk * MROWS + r] = s;
        }
        if (hit) d_tgl[r] = tval;
    }
}

// ---- kernel 6: combine partials -> per-row loss ----
__global__ void combine_kernel() {
    int r = blockIdx.x, tid = threadIdx.x;   // 4096 x 128
    __shared__ float sm[128], ss[128];
    float m = (tid < NBLK) ? d_pm[(size_t)tid * MROWS + r] : -3e38f;
    float s = (tid < NBLK) ? d_ps[(size_t)tid * MROWS + r] : 0.f;
    sm[tid] = m;
    __syncthreads();
    for (int off = 64; off; off >>= 1) {
        if (tid < off) sm[tid] = fmaxf(sm[tid], sm[tid + off]);
        __syncthreads();
    }
    float M = sm[0];
    ss[tid] = s * fast_exp(m - M);
    __syncthreads();
    for (int off = 64; off; off >>= 1) {
        if (tid < off) ss[tid] += ss[tid + off];
        __syncthreads();
    }
    if (tid == 0) d_rowloss[r] = (M + logf(ss[0])) - d_tgl[r];
}

// ---- kernel 7: mean ----
__global__ void reduce_kernel(float* __restrict__ out) {
    int tid = threadIdx.x;
    float s = 0.f;
    for (int i = tid; i < MROWS; i += 1024) s += d_rowloss[i];
#pragma unroll
    for (int off = 16; off; off >>= 1) s += __shfl_xor_sync(0xffffffffu, s, off);
    __shared__ float sh[32];
    if ((tid & 31) == 0) sh[tid >> 5] = s;
    __syncthreads();
    if (tid < 32) {
        float v = sh[tid];
#pragma unroll
        for (int off = 16; off; off >>= 1) v += __shfl_xor_sync(0xffffffffu, v, off);
        if (tid == 0) out[0] = v * (1.f / MROWS);
    }
}

extern "C" void kernel_launch(void* const* d_in, const int* in_sizes, int n_in,
                              void* d_out, int out_size) {
    const int*   input_ids  = (const int*)  d_in[0];
    const int*   target_ids = (const int*)  d_in[1];
    const float* core       = (const float*)d_in[2];
    const float* h0         = (const float*)d_in[3];
    const float* pos_embed  = (const float*)d_in[4];
    const float* W1         = (const float*)d_in[5];
    const float* b1         = (const float*)d_in[6];
    const float* W2         = (const float*)d_in[7];
    const float* b2         = (const float*)d_in[8];
    const float* obias      = (const float*)d_in[9];
    const float* ln_gamma   = (const float*)d_in[10];
    const float* ln_beta    = (const float*)d_in[11];
    float* out = (float*)d_out;

    cudaFuncSetAttribute(pass1_kernel, cudaFuncAttributeMaxDynamicSharedMemorySize, P1_SMEM);

    mod_kernel<<<TT, 128>>>(pos_embed, W1, b1, W2, b2);
    convert_core_kernel<<<(int)(((size_t)CHI * V * CHI / 2) / 256), 256>>>(core);
    scan_kernel<<<BB, 64>>>(input_ids, core, h0, ln_gamma, ln_beta);
    for (int h = 0; h < 2; h++) {
        pass1_kernel<<<dim3(2, V / 8), 128, P1_SMEM>>>(h * THALF);
        pass2_kernel<<<dim3(NBLK, THALF), 128>>>(h * THALF, target_ids, obias);
    }
    combine_kernel<<<MROWS, 128>>>();
    reduce_kernel<<<1, 1024>>>(out);
}

// round 15
// speedup vs baseline: 1.5494x; 1.0057x over previous
#include <cuda_runtime.h>
#include <cuda_fp16.h>
#include <cstdint>

#define V      32000
#define CHI    64
#define TT     512
#define BB     8
#define KTOT   4096
#define MROWS  4096
#define NBLK   125          // V / 256
#define THALF  256          // t values per half-pass
#define LN_EPS 1e-5f

// ---- scratch (device globals; no allocs allowed) ----
__device__ float  d_ml[TT * CHI];
__device__ float  d_mr[TT * CHI];
__device__ __half d_mrh[TT * CHI];
__device__ float  d_Hmod[MROWS * CHI];
__device__ __half d_coreh2[(size_t)CHI * V * CHI];       // fp16 core, layout [i][v][j]
__device__ __half d_D[(size_t)THALF * V * CHI];          // D[tloc][v][i], 1.05 GB
__device__ float  d_pm[(size_t)NBLK * MROWS];
__device__ float  d_ps[(size_t)NBLK * MROWS];
__device__ float  d_tgl[MROWS];
__device__ float  d_rowloss[MROWS];

// ---- helpers ----
__device__ __forceinline__ uint32_t smem_u32(const void* p) {
    uint32_t a;
    asm("{ .reg .u64 t; cvta.to.shared.u64 t, %1; cvt.u32.u64 %0, t; }" : "=r"(a) : "l"(p));
    return a;
}
__device__ __forceinline__ void cp_async16(uint32_t s, const void* g) {
    asm volatile("cp.async.cg.shared.global [%0], [%1], 16;\n" :: "r"(s), "l"(g) : "memory");
}
#define CP_COMMIT() asm volatile("cp.async.commit_group;\n" ::: "memory")
#define CP_WAIT1()  asm volatile("cp.async.wait_group 1;\n" ::: "memory")
#define CP_WAIT0()  asm volatile("cp.async.wait_group 0;\n" ::: "memory")

#define LDSM4(r, addr) \
    asm volatile("ldmatrix.sync.aligned.m8n8.x4.shared.b16 {%0,%1,%2,%3}, [%4];" \
        : "=r"((r)[0]), "=r"((r)[1]), "=r"((r)[2]), "=r"((r)[3]) : "r"(addr))

#define MMA16816(d, a, b0, b1) \
    asm volatile("mma.sync.aligned.m16n8k16.row.col.f32.f16.f16.f32 " \
        "{%0,%1,%2,%3}, {%4,%5,%6,%7}, {%8,%9}, {%0,%1,%2,%3};" \
        : "+f"((d)[0]), "+f"((d)[1]), "+f"((d)[2]), "+f"((d)[3]) \
        : "r"((a)[0]), "r"((a)[1]), "r"((a)[2]), "r"((a)[3]), "r"(b0), "r"(b1))

__device__ __forceinline__ float fast_exp(float x) {   // exp(x), x <= 0
    if (x < -87.0f) return 0.f;
    float y = x * 1.44269504f;
    float n = rintf(y);
    float f = y - n;
    float p = 1.53938e-4f;
    p = fmaf(p, f, 1.33336e-3f);
    p = fmaf(p, f, 9.61813e-3f);
    p = fmaf(p, f, 5.55041e-2f);
    p = fmaf(p, f, 2.402265e-1f);
    p = fmaf(p, f, 6.931472e-1f);
    p = fmaf(p, f, 1.0f);
    return p * __int_as_float(((int)n + 127) << 23);
}

// ---- kernel 1: position MLP -> ml, mr (+ fp16 mr) ----
__global__ void mod_kernel(const float* __restrict__ pos,
                           const float* __restrict__ W1, const float* __restrict__ b1,
                           const float* __restrict__ W2, const float* __restrict__ b2) {
    int t = blockIdx.x, tid = threadIdx.x;   // 512 x 128
    __shared__ float pe[64];
    __shared__ float hm[128];
    if (tid < 64) pe[tid] = pos[t * 64 + tid];
    __syncthreads();
    float s = b1[tid];
#pragma unroll
    for (int p = 0; p < 64; p++) s += pe[p] * W1[p * 128 + tid];
    hm[tid] = s * 0.5f * (1.0f + erff(s * 0.7071067811865475f));
    __syncthreads();
    float s2 = b2[tid];
#pragma unroll
    for (int h = 0; h < 128; h++) s2 += hm[h] * W2[h * 128 + tid];
    float vm = 1.0f + 0.5f * tanhf(s2);
    if (tid < 64) d_ml[t * 64 + tid] = vm;
    else {
        d_mr[t * 64 + (tid - 64)]  = vm;
        d_mrh[t * 64 + (tid - 64)] = __float2half(vm);
    }
}

// ---- kernel 2: core fp32 -> fp16, identity layout [i][v][j] ----
__global__ void convert_core_kernel(const float* __restrict__ core) {
    long long n2 = (long long)blockIdx.x * blockDim.x + threadIdx.x;  // CHI*V*CHI/2
    const float2 f = reinterpret_cast<const float2*>(core)[n2];
    reinterpret_cast<__half2*>(d_coreh2)[n2] = __floats2half2_rn(f.x, f.y);
}

// ---- kernel 3: sequential scan (unchanged, verified) ----
__global__ void scan_kernel(const int* __restrict__ ids, const float* __restrict__ core,
                            const float* __restrict__ h0,
                            const float* __restrict__ gam, const float* __restrict__ bet) {
    __shared__ float sl[2][64 * 64];
    __shared__ float hm[64];
    __shared__ float red[4];
    int b = blockIdx.x, tid = threadIdx.x, lane = tid & 31, wid = tid >> 5;
    float h = h0[tid], g = gam[tid], be = bet[tid];
    uint32_t sb[2] = { smem_u32(&sl[0][0]), smem_u32(&sl[1][0]) };
    {
        int x = ids[b * TT];
        for (int gq = tid; gq < 1024; gq += 64) {
            int i = gq >> 4, c = gq & 15;
            cp_async16(sb[0] + i * 256 + c * 16,
                       core + (size_t)i * ((size_t)V * 64) + (size_t)x * 64 + c * 4);
        }
        CP_COMMIT();
    }
    for (int t = 0; t < TT; t++) {
        if (t + 1 < TT) {
            int x = ids[b * TT + t + 1];
            uint32_t base = sb[(t + 1) & 1];
            for (int gq = tid; gq < 1024; gq += 64) {
                int i = gq >> 4, c = gq & 15;
                cp_async16(base + i * 256 + c * 16,
                           core + (size_t)i * ((size_t)V * 64) + (size_t)x * 64 + c * 4);
            }
        }
        CP_COMMIT();
        CP_WAIT1();
        float hv = h * d_ml[t * 64 + tid];
        hm[tid] = hv;
        d_Hmod[(t * 8 + b) * 64 + tid] = hv;
        __syncthreads();
        const float* s = &sl[t & 1][0];
        float y = 0.f;
#pragma unroll
        for (int i = 0; i < 64; i++) y += hm[i] * s[i * 64 + tid];
        y *= d_mr[t * 64 + tid];
        float su = y, q = y * y;
#pragma unroll
        for (int off = 16; off; off >>= 1) {
            su += __shfl_xor_sync(0xffffffffu, su, off);
            q  += __shfl_xor_sync(0xffffffffu, q,  off);
        }
        if (lane == 0) { red[wid * 2] = su; red[wid * 2 + 1] = q; }
        __syncthreads();
        float S = red[0] + red[2], Q = red[1] + red[3];
        float mu = S * (1.f / 64.f);
        float var = Q * (1.f / 64.f) - mu * mu;
        h = (y - mu) * rsqrtf(var + LN_EPS) * g + be;
        __syncthreads();
    }
}

// ---- kernel 4 (pass 1): D[tloc][v][i] = sum_j mr[t][j] * core[i][v][j] ----
// per-v GEMM: M=t (tile 128), N=i (64), K=j (64). Block: 4 v's, 128 threads.
// v-group = 4 (was 8): smem 48KB -> 4 blocks/SM -> 16 warps/SM (occupancy fix)
// smem: A (mr tile, 128x64 half, 16KB) @0 ; B[vv] (64x64 half, 8KB) @16384+vv*8192
#define P1_SMEM (16384 + 4 * 8192)
__global__ void __launch_bounds__(128, 4)
pass1_kernel(int t_base) {
    extern __shared__ __align__(16) char p1sm[];
    const int tid = threadIdx.x, w = tid >> 5, lane = tid & 31;
    const int lr = lane & 15, lc = lane >> 4;
    const int t0 = blockIdx.x * 128;        // local t within half [0,256)
    const int vg = blockIdx.y * 4;
    const uint32_t sb = smem_u32(p1sm);

    // load A: 128 rows x 128B (swizzled)
#pragma unroll
    for (int it = 0; it < 8; it++) {
        int idx = tid + it * 128;
        int row = idx >> 3, c = idx & 7;
        uint32_t o = (uint32_t)(row * 128 + c * 16);
        o ^= (uint32_t)((row & 7) << 4);
        cp_async16(sb + o, d_mrh + (size_t)(t_base + t0 + row) * 64 + c * 8);
    }
    // load B: 4 v x 64 rows x 128B
#pragma unroll
    for (int it = 0; it < 16; it++) {
        int idx = tid + it * 128;
        int vv = idx >> 9, rem = idx & 511;
        int row = rem >> 3, c = rem & 7;
        uint32_t o = (uint32_t)(row * 128 + c * 16);
        o ^= (uint32_t)((row & 7) << 4);
        cp_async16(sb + 16384u + (uint32_t)vv * 8192u + o,
                   d_coreh2 + ((size_t)row * V + (vg + vv)) * 64 + c * 8);
    }
    CP_COMMIT();
    CP_WAIT0();
    __syncthreads();

    const int t4 = lane >> 2, t2 = (lane & 3) * 2;
    for (int vv = 0; vv < 4; vv++) {
        float acc[2][8][4];
#pragma unroll
        for (int im = 0; im < 2; im++)
#pragma unroll
            for (int j8 = 0; j8 < 8; j8++)
#pragma unroll
                for (int c = 0; c < 4; c++) acc[im][j8][c] = 0.f;

        const uint32_t bb = sb + 16384u + (uint32_t)vv * 8192u;
#pragma unroll
        for (int ks = 0; ks < 4; ks++) {
            const int koff = ks * 32 + lc * 16;
            uint32_t Af[2][4];
#pragma unroll
            for (int im = 0; im < 2; im++) {
                int row = w * 32 + im * 16 + lr;
                uint32_t o = (uint32_t)(row * 128 + koff);
                o ^= (uint32_t)((row & 7) << 4);
                LDSM4(Af[im], sb + o);
            }
            uint32_t Bf[4][4];
#pragma unroll
            for (int jn = 0; jn < 4; jn++) {
                int row = jn * 16 + lr;
                uint32_t o = (uint32_t)(row * 128 + koff);
                o ^= (uint32_t)((row & 7) << 4);
                LDSM4(Bf[jn], bb + o);
            }
#pragma unroll
            for (int im = 0; im < 2; im++)
#pragma unroll
                for (int j8 = 0; j8 < 8; j8++)
                    MMA16816(acc[im][j8], Af[im],
                             Bf[j8 >> 1][j8 & 1], Bf[j8 >> 1][(j8 & 1) + 2]);
        }
        // store fragments to D[tloc][v][i] (i contiguous, half2)
        const size_t vbase = (size_t)(vg + vv) * 64;
#pragma unroll
        for (int im = 0; im < 2; im++) {
            int r0 = t0 + w * 32 + im * 16 + t4;
#pragma unroll
            for (int j8 = 0; j8 < 8; j8++) {
                int gc = j8 * 8 + t2;
                *reinterpret_cast<__half2*>(d_D + (size_t)r0 * (V * 64) + vbase + gc) =
                    __floats2half2_rn(acc[im][j8][0], acc[im][j8][1]);
                *reinterpret_cast<__half2*>(d_D + (size_t)(r0 + 8) * (V * 64) + vbase + gc) =
                    __floats2half2_rn(acc[im][j8][2], acc[im][j8][3]);
            }
        }
    }
}

// ---- kernel 5 (pass 2): logits[(t,b),v] = sum_i hmod[(t,b),i] * D[t][v][i], fused softmax
// block = (vblk 256 v's, one t). M=16 (8 valid b rows), N=256, K=64.
__global__ void __launch_bounds__(128)
pass2_kernel(int t_base, const int* __restrict__ tgt, const float* __restrict__ bias) {
    __shared__ __align__(16) __half Dt[256 * 64];   // rows v (128B, swizzled)
    __shared__ __align__(16) __half Ah[16 * 64];    // rows b (128B, swizzled)
    __shared__ float accs[8 * 256];
    __shared__ float bs[256];
    const int tid = threadIdx.x, w = tid >> 5, lane = tid & 31;
    const int lr = lane & 15, lc = lane >> 4;
    const int vblk = blockIdx.x, v0 = vblk * 256;
    const int tloc = blockIdx.y, tg_t = t_base + tloc;
    const uint32_t db = smem_u32(Dt), abh = smem_u32(Ah);

    // load D tile: 256 rows x 128B
#pragma unroll
    for (int it = 0; it < 16; it++) {
        int idx = tid + it * 128;
        int row = idx >> 3, c = idx & 7;
        uint32_t o = (uint32_t)(row * 128 + c * 16);
        o ^= (uint32_t)((row & 7) << 4);
        cp_async16(db + o, d_D + ((size_t)tloc * V + (v0 + row)) * 64 + c * 8);
    }
    CP_COMMIT();
    // build A: rows 0-7 = fp16(hmod[tg_t*8+b]), rows 8-15 = 0 (swizzled stores)
    for (int idx = tid; idx < 1024; idx += 128) {
        int b = idx >> 6, i = idx & 63;
        __half hv = (b < 8) ? __float2half(d_Hmod[(size_t)(tg_t * 8 + b) * 64 + i])
                            : __half(0.f);
        uint32_t o = (uint32_t)(b * 128 + i * 2);
        o ^= (uint32_t)((b & 7) << 4);
        *reinterpret_cast<__half*>(reinterpret_cast<char*>(Ah) + o) = hv;
    }
    bs[tid]       = bias[v0 + tid];
    bs[tid + 128] = bias[v0 + tid + 128];
    CP_WAIT0();
    __syncthreads();

    float acc[8][4];
#pragma unroll
    for (int j8 = 0; j8 < 8; j8++)
#pragma unroll
        for (int c = 0; c < 4; c++) acc[j8][c] = 0.f;

#pragma unroll
    for (int ks = 0; ks < 4; ks++) {
        const int koff = ks * 32 + lc * 16;
        uint32_t Af[4];
        {
            int row = lr;
            uint32_t o = (uint32_t)(row * 128 + koff);
            o ^= (uint32_t)((row & 7) << 4);
            LDSM4(Af, abh + o);
        }
        uint32_t Bf[4][4];
#pragma unroll
        for (int jn = 0; jn < 4; jn++) {
            int row = w * 64 + jn * 16 + lr;
            uint32_t o = (uint32_t)(row * 128 + koff);
            o ^= (uint32_t)((row & 7) << 4);
            LDSM4(Bf[jn], db + o);
        }
#pragma unroll
        for (int j8 = 0; j8 < 8; j8++)
            MMA16816(acc[j8], Af, Bf[j8 >> 1][j8 & 1], Bf[j8 >> 1][(j8 & 1) + 2]);
    }
    // store valid rows (c0,c1: row t4 in 0..7) to accs
    {
        int t4 = lane >> 2, t2 = (lane & 3) * 2;
#pragma unroll
        for (int j8 = 0; j8 < 8; j8++) {
            int gc = w * 64 + j8 * 8 + t2;
            accs[t4 * 256 + gc]     = acc[j8][0];
            accs[t4 * 256 + gc + 1] = acc[j8][1];
        }
    }
    __syncthreads();

    // fused partial softmax: 8 rows x 256 cols; 16 threads per row
    {
        int row = tid >> 4, seg = tid & 15;
        int r = tg_t * 8 + row;                      // global row (t*8+b)
        int tg = tgt[row * TT + tg_t];
        float m = -1e30f, s = 0.f, tval = 0.f;
        bool hit = false;
#pragma unroll
        for (int c0 = 0; c0 < 16; c0++) {
            int col = seg * 16 + c0;
            float x = accs[row * 256 + col] + bs[col];
            if (v0 + col == tg) { tval = x; hit = true; }
            m = fmaxf(m, x);
        }
        float s0 = 0.f;
#pragma unroll
        for (int c0 = 0; c0 < 16; c0++) {
            int col = seg * 16 + c0;
            s0 += fast_exp(accs[row * 256 + col] + bs[col] - m);
        }
        s = s0;
#pragma unroll
        for (int off = 1; off < 16; off <<= 1) {
            float m2 = __shfl_xor_sync(0xffffffffu, m, off);
            float s2 = __shfl_xor_sync(0xffffffffu, s, off);
            float M = fmaxf(m, m2);
            s = s * fast_exp(m - M) + s2 * fast_exp(m2 - M);
            m = M;
        }
        if (seg == 0) {
            d_pm[(size_t)vblk * MROWS + r] = m;
            d_ps[(size_t)vblk * MROWS + r] = s;
        }
        if (hit) d_tgl[r] = tval;
    }
}

// ---- kernel 6: combine partials -> per-row loss ----
__global__ void combine_kernel() {
    int r = blockIdx.x, tid = threadIdx.x;   // 4096 x 128
    __shared__ float sm[128], ss[128];
    float m = (tid < NBLK) ? d_pm[(size_t)tid * MROWS + r] : -3e38f;
    float s = (tid < NBLK) ? d_ps[(size_t)tid * MROWS + r] : 0.f;
    sm[tid] = m;
    __syncthreads();
    for (int off = 64; off; off >>= 1) {
        if (tid < off) sm[tid] = fmaxf(sm[tid], sm[tid + off]);
        __syncthreads();
    }
    float M = sm[0];
    ss[tid] = s * fast_exp(m - M);
    __syncthreads();
    for (int off = 64; off; off >>= 1) {
        if (tid < off) ss[tid] += ss[tid + off];
        __syncthreads();
    }
    if (tid == 0) d_rowloss[r] = (M + logf(ss[0])) - d_tgl[r];
}

// ---- kernel 7: mean ----
__global__ void reduce_kernel(float* __restrict__ out) {
    int tid = threadIdx.x;
    float s = 0.f;
    for (int i = tid; i < MROWS; i += 1024) s += d_rowloss[i];
#pragma unroll
    for (int off = 16; off; off >>= 1) s += __shfl_xor_sync(0xffffffffu, s, off);
    __shared__ float sh[32];
    if ((tid & 31) == 0) sh[tid >> 5] = s;
    __syncthreads();
    if (tid < 32) {
        float v = sh[tid];
#pragma unroll
        for (int off = 16; off; off >>= 1) v += __shfl_xor_sync(0xffffffffu, v, off);
        if (tid == 0) out[0] = v * (1.f / MROWS);
    }
}

extern "C" void kernel_launch(void* const* d_in, const int* in_sizes, int n_in,
                              void* d_out, int out_size) {
    const int*   input_ids  = (const int*)  d_in[0];
    const int*   target_ids = (const int*)  d_in[1];
    const float* core       = (const float*)d_in[2];
    const float* h0         = (const float*)d_in[3];
    const float* pos_embed  = (const float*)d_in[4];
    const float* W1         = (const float*)d_in[5];
    const float* b1         = (const float*)d_in[6];
    const float* W2         = (const float*)d_in[7];
    const float* b2         = (const float*)d_in[8];
    const float* obias      = (const float*)d_in[9];
    const float* ln_gamma   = (const float*)d_in[10];
    const float* ln_beta    = (const float*)d_in[11];
    float* out = (float*)d_out;

    cudaFuncSetAttribute(pass1_kernel, cudaFuncAttributeMaxDynamicSharedMemorySize, P1_SMEM);

    mod_kernel<<<TT, 128>>>(pos_embed, W1, b1, W2, b2);
    convert_core_kernel<<<(int)(((size_t)CHI * V * CHI / 2) / 256), 256>>>(core);
    scan_kernel<<<BB, 64>>>(input_ids, core, h0, ln_gamma, ln_beta);
    for (int h = 0; h < 2; h++) {
        pass1_kernel<<<dim3(2, V / 4), 128, P1_SMEM>>>(h * THALF);
        pass2_kernel<<<dim3(NBLK, THALF), 128>>>(h * THALF, target_ids, obias);
    }
    combine_kernel<<<MROWS, 128>>>();
    reduce_kernel<<<1, 1024>>>(out);
}